// round 16
// baseline (speedup 1.0000x reference)
#include <cuda_runtime.h>
#include <cuda_fp16.h>
#include <stdint.h>

// SparseLinear: out[n,64] = segment_sum(value * W[col,:], rows) + bias
// R14 pipeline (memset counts, fused cvt+fill int4-vectorized, 96-slot rows)
// with a leaner quarter-warp HFMA2 SpMM: per-lane pre-splatted operands, so
// the inner loop is 2 SHFL + LDG.128 + 4 HFMA2 per 4 nnz.

#define OUTF    64
#define N_MAX   100032
#define NNZ_MAX 4000000
#define INF_MAX 5120
#define S       96            // slots per row; Poisson(40), P(>=96) ~ 1e-12
#define OVF_MAX 4096
#define CVTB    160           // blocks of k_fill dedicated to W convert

__device__ int      g_counts[N_MAX + 1];           // [+1] = overflow counter
__device__ unsigned g_slots[(size_t)N_MAX * S];    // col<<16 | fp16(value); >=cnt stays 0
__device__ int2     g_ovf[OVF_MAX];                // {row, pack}
__device__ __half   g_wh[INF_MAX * OUTF];          // fp16 W (row = 128B)

// ---------------- fill: cvt (first CVTB blocks) + count-and-place, 4 nnz/thread ----------------
__global__ void __launch_bounds__(256)
k_fill(const int* __restrict__ rows, const int* __restrict__ cols,
       const float* __restrict__ vals, int nnz,
       const float* __restrict__ W, int wtot, int n) {
    int b = blockIdx.x, t = threadIdx.x;
    if (b < CVTB) {    // convert W fp32 -> fp16, grid-stride
        for (int i = b * 256 + t; i < wtot; i += CVTB * 256)
            g_wh[i] = __float2half_rn(W[i]);
        return;
    }
    int* ovfcnt = &g_counts[n];
    int i = ((b - CVTB) * 256 + t) * 4;
    if (i + 3 < nnz) {
        int4   r4 = *(const int4*)(rows + i);
        int4   c4 = *(const int4*)(cols + i);
        float4 v4 = *(const float4*)(vals + i);
        int rr[4] = {r4.x, r4.y, r4.z, r4.w};
        int cc[4] = {c4.x, c4.y, c4.z, c4.w};
        float vv[4] = {v4.x, v4.y, v4.z, v4.w};
        unsigned pk[4]; int rk[4];
        #pragma unroll
        for (int j = 0; j < 4; ++j)
            pk[j] = ((unsigned)cc[j] << 16)
                  | (unsigned)__half_as_ushort(__float2half_rn(vv[j]));
        #pragma unroll
        for (int j = 0; j < 4; ++j)                // 4 independent ATOMGs in flight
            rk[j] = atomicAdd(&g_counts[rr[j]], 1);
        #pragma unroll
        for (int j = 0; j < 4; ++j) {
            if (rk[j] < S) {
                __stcs(&g_slots[(size_t)rr[j] * S + rk[j]], pk[j]);
            } else {
                int o = atomicAdd(ovfcnt, 1);
                if (o < OVF_MAX) g_ovf[o] = make_int2(rr[j], (int)pk[j]);
            }
        }
    } else {
        for (int k = i; k < nnz; ++k) {
            int r = rows[k];
            unsigned pk = ((unsigned)cols[k] << 16)
                        | (unsigned)__half_as_ushort(__float2half_rn(vals[k]));
            int rank = atomicAdd(&g_counts[r], 1);
            if (rank < S) {
                __stcs(&g_slots[(size_t)r * S + rank], pk);
            } else {
                int o = atomicAdd(ovfcnt, 1);
                if (o < OVF_MAX) g_ovf[o] = make_int2(r, (int)pk);
            }
        }
    }
}

// ---------------- quarter-warp SpMM, pre-splatted HFMA2 inner loop ----------------
__global__ void __launch_bounds__(256)
k_spmm(const float* __restrict__ bias, float* __restrict__ out, int n) {
    int row  = (blockIdx.x * blockDim.x + threadIdx.x) >> 5;
    int lane = threadIdx.x & 31;
    if (row >= n) return;
    int q  = lane >> 3;            // quarter 0..3: processes nnz j+q
    int cg = lane & 7;             // owns cols [8*cg, 8*cg+7]

    const char* __restrict__ wq = (const char*)g_wh + cg * 16;   // 8 fp16 cols
    float4 a0 = make_float4(0.f, 0.f, 0.f, 0.f);
    float4 a1 = make_float4(0.f, 0.f, 0.f, 0.f);

    int cnt = g_counts[row];
    if (cnt > S) cnt = S;
    const unsigned* __restrict__ sl = &g_slots[(size_t)row * S];

    for (int base = 0; base < cnt; base += 32) {
        // unpredicated: max index 64+31=95 < S; slots >= cnt are zero (inert)
        unsigned u = sl[base + lane];              // 128B coalesced strip
        // pre-splat this lane's operands once (amortized over 32 lanes)
        int bo = (int)(u >> 16) << 7;              // fp16 W row byte offset
        __half2 vs = __half2half2(__ushort_as_half((unsigned short)(u & 0xFFFFu)));
        unsigned vbits = *(unsigned*)&vs;          // splatted half2 bits
        int m = cnt - base; if (m > 32) m = 32;
        __half2 h0 = __float2half2_rn(0.f), h1 = h0, h2 = h0, h3 = h0;
        #pragma unroll 2
        for (int j = 0; j < m; j += 4) {           // padded lanes: v=0 -> safe
            int      b2 = __shfl_sync(0xFFFFFFFFu, bo,    j + q);
            unsigned vb = __shfl_sync(0xFFFFFFFFu, vbits, j + q);
            __half2 vh = *(__half2*)&vb;
            uint4 wr = *(const uint4*)(wq + b2);   // 16B = 8 fp16 cols
            h0 = __hfma2(vh, *(const __half2*)&wr.x, h0);
            h1 = __hfma2(vh, *(const __half2*)&wr.y, h1);
            h2 = __hfma2(vh, *(const __half2*)&wr.z, h2);
            h3 = __hfma2(vh, *(const __half2*)&wr.w, h3);
        }
        float2 f;                                  // flush strip to fp32
        f = __half22float2(h0); a0.x += f.x; a0.y += f.y;
        f = __half22float2(h1); a0.z += f.x; a0.w += f.y;
        f = __half22float2(h2); a1.x += f.x; a1.y += f.y;
        f = __half22float2(h3); a1.z += f.x; a1.w += f.y;
    }

    // inline overflow fixup BEFORE merge (statistically empty); quarter 0 only
    int oc = g_counts[n];
    if (oc > 0) {
        if (oc > OVF_MAX) oc = OVF_MAX;
        for (int i = 0; i < oc; ++i) {
            int2 it = g_ovf[i];
            if (it.x == row && q == 0) {
                unsigned up = (unsigned)it.y;
                float v = __half2float(__ushort_as_half((unsigned short)(up & 0xFFFFu)));
                uint4 wr = *(const uint4*)(wq + ((int)(up >> 16) << 7));
                float2 w01 = __half22float2(*(const __half2*)&wr.x);
                float2 w23 = __half22float2(*(const __half2*)&wr.y);
                float2 w45 = __half22float2(*(const __half2*)&wr.z);
                float2 w67 = __half22float2(*(const __half2*)&wr.w);
                a0.x = fmaf(v, w01.x, a0.x);  a0.y = fmaf(v, w01.y, a0.y);
                a0.z = fmaf(v, w23.x, a0.z);  a0.w = fmaf(v, w23.y, a0.w);
                a1.x = fmaf(v, w45.x, a1.x);  a1.y = fmaf(v, w45.y, a1.y);
                a1.z = fmaf(v, w67.x, a1.z);  a1.w = fmaf(v, w67.y, a1.w);
            }
        }
    }

    // merge quarters: same cg across lane bits 3,4
    #pragma unroll
    for (int d = 8; d <= 16; d <<= 1) {
        a0.x += __shfl_xor_sync(0xFFFFFFFFu, a0.x, d);
        a0.y += __shfl_xor_sync(0xFFFFFFFFu, a0.y, d);
        a0.z += __shfl_xor_sync(0xFFFFFFFFu, a0.z, d);
        a0.w += __shfl_xor_sync(0xFFFFFFFFu, a0.w, d);
        a1.x += __shfl_xor_sync(0xFFFFFFFFu, a1.x, d);
        a1.y += __shfl_xor_sync(0xFFFFFFFFu, a1.y, d);
        a1.z += __shfl_xor_sync(0xFFFFFFFFu, a1.z, d);
        a1.w += __shfl_xor_sync(0xFFFFFFFFu, a1.w, d);
    }

    if (q == 0) {
        float4 b0 = ((const float4*)bias)[2 * cg];
        float4 b1 = ((const float4*)bias)[2 * cg + 1];
        a0.x += b0.x; a0.y += b0.y; a0.z += b0.z; a0.w += b0.w;
        a1.x += b1.x; a1.y += b1.y; a1.z += b1.z; a1.w += b1.w;
        float4* orow = (float4*)out + (size_t)row * 16;
        orow[2 * cg]     = a0;                     // 8 lanes x 32B = 256B row
        orow[2 * cg + 1] = a1;
    }
}

// ---------------- launch ----------------
extern "C" void kernel_launch(void* const* d_in, const int* in_sizes, int n_in,
                              void* d_out, int out_size) {
    const int*   index  = (const int*)d_in[0];    // [2, nnz]
    const float* value  = (const float*)d_in[1];  // [nnz]
    const float* weight = (const float*)d_in[3];  // [in_f, 64]
    const float* bias   = (const float*)d_in[4];  // [64]
    float* out = (float*)d_out;

    int nnz  = in_sizes[1];
    int n    = out_size / OUTF;
    int wtot = in_sizes[3];

    const int* rows = index;
    const int* cols = index + nnz;

    void* p = nullptr;
    cudaGetSymbolAddress(&p, g_counts);
    cudaMemsetAsync(p, 0, ((size_t)n + 1) * sizeof(int));

    int fb = CVTB + (nnz / 4 + 255) / 256 + 1;    // +1 covers the scalar tail
    k_fill<<<fb, 256>>>(rows, cols, value, nnz, weight, wtot, n);

    int blocks = (n * 32 + 255) / 256;
    k_spmm<<<blocks, 256>>>(bias, out, n);
}

// round 17
// speedup vs baseline: 1.1019x; 1.1019x over previous
#include <cuda_runtime.h>
#include <cuda_fp16.h>
#include <stdint.h>

// SparseLinear: out[n,64] = segment_sum(value * W[col,:], rows) + bias
// R14 pipeline; slot stores use default writeback (L2-resident for SpMM
// re-read) and S=72 (28MB slot region) to cut L2 capacity pressure.

#define OUTF    64
#define N_MAX   100032
#define NNZ_MAX 4000000
#define INF_MAX 5120
#define S       72            // slots per row; Poisson(40), P(>72) ~ 3e-7
#define OVF_MAX 4096
#define CVTB    160           // blocks of k_fill dedicated to W convert

__device__ int      g_counts[N_MAX + 1];           // [+1] = overflow counter
__device__ unsigned g_slots[(size_t)N_MAX * S];    // col<<16 | fp16(value)
__device__ int2     g_ovf[OVF_MAX];                // {row, pack}
__device__ __half   g_wh[INF_MAX * OUTF];          // fp16 W (row = 128B)

// ---------------- fill: cvt (first CVTB blocks) + count-and-place, 4 nnz/thread ----------------
__global__ void __launch_bounds__(256)
k_fill(const int* __restrict__ rows, const int* __restrict__ cols,
       const float* __restrict__ vals, int nnz,
       const float* __restrict__ W, int wtot, int n) {
    int b = blockIdx.x, t = threadIdx.x;
    if (b < CVTB) {    // convert W fp32 -> fp16, grid-stride
        for (int i = b * 256 + t; i < wtot; i += CVTB * 256)
            g_wh[i] = __float2half_rn(W[i]);
        return;
    }
    int* ovfcnt = &g_counts[n];
    int i = ((b - CVTB) * 256 + t) * 4;
    if (i + 3 < nnz) {
        int4   r4 = *(const int4*)(rows + i);
        int4   c4 = *(const int4*)(cols + i);
        float4 v4 = *(const float4*)(vals + i);
        int rr[4] = {r4.x, r4.y, r4.z, r4.w};
        int cc[4] = {c4.x, c4.y, c4.z, c4.w};
        float vv[4] = {v4.x, v4.y, v4.z, v4.w};
        unsigned pk[4]; int rk[4];
        #pragma unroll
        for (int j = 0; j < 4; ++j)
            pk[j] = ((unsigned)cc[j] << 16)
                  | (unsigned)__half_as_ushort(__float2half_rn(vv[j]));
        #pragma unroll
        for (int j = 0; j < 4; ++j)                // 4 independent ATOMGs in flight
            rk[j] = atomicAdd(&g_counts[rr[j]], 1);
        #pragma unroll
        for (int j = 0; j < 4; ++j) {
            if (rk[j] < S) {
                g_slots[(size_t)rr[j] * S + rk[j]] = pk[j];   // writeback: stay in L2
            } else {
                int o = atomicAdd(ovfcnt, 1);
                if (o < OVF_MAX) g_ovf[o] = make_int2(rr[j], (int)pk[j]);
            }
        }
    } else {
        for (int k = i; k < nnz; ++k) {
            int r = rows[k];
            unsigned pk = ((unsigned)cols[k] << 16)
                        | (unsigned)__half_as_ushort(__float2half_rn(vals[k]));
            int rank = atomicAdd(&g_counts[r], 1);
            if (rank < S) {
                g_slots[(size_t)r * S + rank] = pk;
            } else {
                int o = atomicAdd(ovfcnt, 1);
                if (o < OVF_MAX) g_ovf[o] = make_int2(r, (int)pk);
            }
        }
    }
}

// ---------------- quarter-warp SpMM, HFMA2 inner loop (R11/R14 verbatim) ----------------
__global__ void __launch_bounds__(256)
k_spmm(const float* __restrict__ bias, float* __restrict__ out, int n) {
    int row  = (blockIdx.x * blockDim.x + threadIdx.x) >> 5;
    int lane = threadIdx.x & 31;
    if (row >= n) return;
    int q  = lane >> 3;            // quarter 0..3: processes nnz j+q
    int cg = lane & 7;             // owns cols [8*cg, 8*cg+7]

    const char* __restrict__ wq = (const char*)g_wh + cg * 16;   // 8 fp16 cols
    float4 a0 = make_float4(0.f, 0.f, 0.f, 0.f);
    float4 a1 = make_float4(0.f, 0.f, 0.f, 0.f);

    int cnt = g_counts[row];
    if (cnt > S) cnt = S;
    const unsigned* __restrict__ sl = &g_slots[(size_t)row * S];

    for (int base = 0; base < cnt; base += 32) {
        int k = base + lane;
        unsigned u = (k < cnt) ? sl[k] : 0u;       // coalesced strip
        int m = cnt - base; if (m > 32) m = 32;
        int src = q;
        __half2 h0 = __float2half2_rn(0.f), h1 = h0, h2 = h0, h3 = h0;
        #pragma unroll 2
        for (int j = 0; j < m; j += 4) {           // padded lanes: v=0 -> safe
            unsigned up = __shfl_sync(0xFFFFFFFFu, u, src);
            src += 4;
            int bo = (int)(up >> 16) << 7;         // fp16 W row byte offset
            __half2 vh = __half2half2(__ushort_as_half((unsigned short)(up & 0xFFFFu)));
            uint4 wr = *(const uint4*)(wq + bo);   // 16B = 8 fp16 cols
            h0 = __hfma2(vh, *(const __half2*)&wr.x, h0);
            h1 = __hfma2(vh, *(const __half2*)&wr.y, h1);
            h2 = __hfma2(vh, *(const __half2*)&wr.z, h2);
            h3 = __hfma2(vh, *(const __half2*)&wr.w, h3);
        }
        float2 f;                                  // flush strip to fp32
        f = __half22float2(h0); a0.x += f.x; a0.y += f.y;
        f = __half22float2(h1); a0.z += f.x; a0.w += f.y;
        f = __half22float2(h2); a1.x += f.x; a1.y += f.y;
        f = __half22float2(h3); a1.z += f.x; a1.w += f.y;
    }

    // inline overflow fixup BEFORE merge (statistically empty); quarter 0 only
    int oc = g_counts[n];
    if (oc > 0) {
        if (oc > OVF_MAX) oc = OVF_MAX;
        for (int i = 0; i < oc; ++i) {
            int2 it = g_ovf[i];
            if (it.x == row && q == 0) {
                unsigned up = (unsigned)it.y;
                float v = __half2float(__ushort_as_half((unsigned short)(up & 0xFFFFu)));
                uint4 wr = *(const uint4*)(wq + ((int)(up >> 16) << 7));
                float2 w01 = __half22float2(*(const __half2*)&wr.x);
                float2 w23 = __half22float2(*(const __half2*)&wr.y);
                float2 w45 = __half22float2(*(const __half2*)&wr.z);
                float2 w67 = __half22float2(*(const __half2*)&wr.w);
                a0.x = fmaf(v, w01.x, a0.x);  a0.y = fmaf(v, w01.y, a0.y);
                a0.z = fmaf(v, w23.x, a0.z);  a0.w = fmaf(v, w23.y, a0.w);
                a1.x = fmaf(v, w45.x, a1.x);  a1.y = fmaf(v, w45.y, a1.y);
                a1.z = fmaf(v, w67.x, a1.z);  a1.w = fmaf(v, w67.y, a1.w);
            }
        }
    }

    // merge quarters: same cg across lane bits 3,4
    #pragma unroll
    for (int d = 8; d <= 16; d <<= 1) {
        a0.x += __shfl_xor_sync(0xFFFFFFFFu, a0.x, d);
        a0.y += __shfl_xor_sync(0xFFFFFFFFu, a0.y, d);
        a0.z += __shfl_xor_sync(0xFFFFFFFFu, a0.z, d);
        a0.w += __shfl_xor_sync(0xFFFFFFFFu, a0.w, d);
        a1.x += __shfl_xor_sync(0xFFFFFFFFu, a1.x, d);
        a1.y += __shfl_xor_sync(0xFFFFFFFFu, a1.y, d);
        a1.z += __shfl_xor_sync(0xFFFFFFFFu, a1.z, d);
        a1.w += __shfl_xor_sync(0xFFFFFFFFu, a1.w, d);
    }

    if (q == 0) {
        float4 b0 = ((const float4*)bias)[2 * cg];
        float4 b1 = ((const float4*)bias)[2 * cg + 1];
        a0.x += b0.x; a0.y += b0.y; a0.z += b0.z; a0.w += b0.w;
        a1.x += b1.x; a1.y += b1.y; a1.z += b1.z; a1.w += b1.w;
        float4* orow = (float4*)out + (size_t)row * 16;
        orow[2 * cg]     = a0;                     // 8 lanes x 32B = 256B row
        orow[2 * cg + 1] = a1;
    }
}

// ---------------- launch ----------------
extern "C" void kernel_launch(void* const* d_in, const int* in_sizes, int n_in,
                              void* d_out, int out_size) {
    const int*   index  = (const int*)d_in[0];    // [2, nnz]
    const float* value  = (const float*)d_in[1];  // [nnz]
    const float* weight = (const float*)d_in[3];  // [in_f, 64]
    const float* bias   = (const float*)d_in[4];  // [64]
    float* out = (float*)d_out;

    int nnz  = in_sizes[1];
    int n    = out_size / OUTF;
    int wtot = in_sizes[3];

    const int* rows = index;
    const int* cols = index + nnz;

    void* p = nullptr;
    cudaGetSymbolAddress(&p, g_counts);
    cudaMemsetAsync(p, 0, ((size_t)n + 1) * sizeof(int));

    int fb = CVTB + (nnz / 4 + 255) / 256 + 1;    // +1 covers the scalar tail
    k_fill<<<fb, 256>>>(rows, cols, value, nnz, weight, wtot, n);

    int blocks = (n * 32 + 255) / 256;
    k_spmm<<<blocks, 256>>>(bias, out, n);
}